// round 10
// baseline (speedup 1.0000x reference)
#include <cuda_runtime.h>
#include <cuda_bf16.h>

// Problem constants (fixed by the problem spec)
#define NS        4096
#define NQ_TOTAL  32768     // B * N_Q
#define KNN       8
#define FDIM      256
#define FDIM4     (FDIM/4)

#define NSPLIT    8         // sensor slices per query
#define QUARTER   512       // sensors per block (NS / NSPLIT)
#define NPAIR     (QUARTER/2)
#define THREADS   256
#define QPT       2         // queries per thread
#define QPB       (THREADS*QPT)   // 512 queries per block-group
#define GROUP     8         // sensors per inner group (4 pairs)
#define DEPTH     14        // smem candidate slots per (thread,query)
#define TRIG      6         // fold trigger; entering a group cnt<=5 -> max slot 13
#define SLOTB     (THREADS*8)     // 2048 bytes between buffer slots

// Inter-kernel scratch (device globals: allowed; no allocation)
__device__ float2 g_part[NSPLIT * KNN * NQ_TOTAL];  // [split][j][q], 16 MB
__device__ float  g_w  [NQ_TOTAL * KNN];
__device__ int    g_idx[NQ_TOTAL * KNN];

// Branchless sorted insert of (x, xi) into descending (value, idx) top-8 list.
__device__ __forceinline__ void pair_insert(float x, int xi,
                                            float (&v)[KNN], int (&ii)[KNN])
{
#pragma unroll
    for (int j = KNN - 1; j >= 1; --j) {   // v[j-1] still old value here
        bool pjm = x > v[j-1];
        bool pj  = x > v[j];
        v[j]  = pjm ? v[j-1]  : (pj ? x  : v[j]);
        ii[j] = pjm ? ii[j-1] : (pj ? xi : ii[j]);
    }
    bool p0 = x > v[0];
    v[0]  = p0 ? x  : v[0];
    ii[0] = p0 ? xi : ii[0];
}

// Fused hit op: ONE compare feeds both the predicated store and the
// predicated cursor bump. 3 instructions, zero branches, no dup FSETP/SEL.
__device__ __forceinline__ void score_op(unsigned& a, float t, float thr, float fi)
{
    asm volatile(
        "{\n\t"
        ".reg .pred p;\n\t"
        "setp.gt.f32 p, %1, %2;\n\t"
        "@p st.shared.v2.f32 [%0], {%1, %3};\n\t"
        "@p add.u32 %0, %0, %4;\n\t"
        "}"
        : "+r"(a)
        : "f"(t), "f"(thr), "f"(fi), "r"((unsigned)SLOTB)
        : "memory");
}

// Packed f32x2 fma (Blackwell; bit-identical per-lane to scalar fmaf)
__device__ __forceinline__ unsigned long long fma2(unsigned long long a,
                                                   unsigned long long b,
                                                   unsigned long long c)
{
    unsigned long long d;
    asm("fma.rn.f32x2 %0, %1, %2, %3;" : "=l"(d) : "l"(a), "l"(b), "l"(c));
    return d;
}
__device__ __forceinline__ unsigned long long pack2(float lo, float hi)
{
    unsigned long long r;
    asm("mov.b64 %0, {%1, %2};" : "=l"(r) : "f"(lo), "f"(hi));
    return r;
}
__device__ __forceinline__ void unpack2(unsigned long long v, float& lo, float& hi)
{
    asm("mov.b64 {%0, %1}, %2;" : "=f"(lo), "=f"(hi) : "l"(v));
}

// ---------------------------------------------------------------------------
// Scan kernel. Block = (query group of 512) x (sensor slice of 512).
// Sensor-pair SoA tile: t2[2p] = {x0,x1 | y0,y1}, t2[2p+1] = {z0,z1 | -w0,-w1}
// where w = 0.5*|s|^2. Score t = q.s - 0.5|s|^2 per lane of fma.rn.f32x2;
// max-t == nearest. Hit handling is the 3-instruction fused predicated op.
// Warp-uniform folds drain the smem buffer into register-resident sorted top-8.
// ---------------------------------------------------------------------------
__global__ void __launch_bounds__(THREADS) scan_kernel(const float* __restrict__ qc,
                                                       const float* __restrict__ sc)
{
    extern __shared__ float4 tile[];                          // QUARTER*16B = 8 KB
    float2* buf0 = reinterpret_cast<float2*>(tile + QUARTER); // [DEPTH][THREADS] 28 KB
    float2* buf1 = buf0 + DEPTH * THREADS;                    // [DEPTH][THREADS] 28 KB

    const int tid    = threadIdx.x;
    const int split  = blockIdx.x & (NSPLIT - 1);
    const int qgroup = blockIdx.x >> 3;
    const int sbase  = split * QUARTER;
    const int q0     = qgroup * QPB + tid;
    const int q1     = q0 + THREADS;

    // Stage this slice as sensor-pairs (one pair per thread)
    for (int p = tid; p < NPAIR; p += THREADS) {
        const int s = sbase + 2 * p;
        float x0 = sc[3*s+0], y0 = sc[3*s+1], z0 = sc[3*s+2];
        float x1 = sc[3*s+3], y1 = sc[3*s+4], z1 = sc[3*s+5];
        tile[2*p]   = make_float4(x0, x1, y0, y1);
        tile[2*p+1] = make_float4(z0, z1,
                                  -0.5f * (x0*x0 + y0*y0 + z0*z0),
                                  -0.5f * (x1*x1 + y1*y1 + z1*z1));
    }
    __syncthreads();

    const float qx0 = qc[3*q0+0], qy0 = qc[3*q0+1], qz0 = qc[3*q0+2];
    const float qx1 = qc[3*q1+0], qy1 = qc[3*q1+1], qz1 = qc[3*q1+2];
    const unsigned long long qx0d = pack2(qx0, qx0), qy0d = pack2(qy0, qy0),
                             qz0d = pack2(qz0, qz0);
    const unsigned long long qx1d = pack2(qx1, qx1), qy1d = pack2(qy1, qy1),
                             qz1d = pack2(qz1, qz1);

    float v0[KNN], v1[KNN];
    int   i0[KNN], i1[KNN];
#pragma unroll
    for (int j = 0; j < KNN; j++) {
        v0[j] = -3.0e38f; i0[j] = 0;
        v1[j] = -3.0e38f; i1[j] = 0;
    }

    const unsigned base0 = (unsigned)__cvta_generic_to_shared(buf0) + tid * 8u;
    const unsigned base1 = (unsigned)__cvta_generic_to_shared(buf1) + tid * 8u;
    const unsigned lim0  = base0 + TRIG * SLOTB;
    const unsigned lim1  = base1 + TRIG * SLOTB;

    unsigned a0 = base0, a1 = base1;
    float thr0 = -3.0e38f, thr1 = -3.0e38f;

    const ulonglong2* __restrict__ t2 = reinterpret_cast<const ulonglong2*>(tile);

    for (int s0 = 0; s0 < QUARTER; s0 += GROUP) {
#pragma unroll
        for (int up = 0; up < GROUP / 2; up++) {
            const int p = (s0 >> 1) + up;
            ulonglong2 av = t2[2*p];       // (x0,x1) | (y0,y1)
            ulonglong2 bv = t2[2*p+1];     // (z0,z1) | (-w0,-w1)

            unsigned long long r0 = fma2(qx0d, av.x, bv.y);
            r0 = fma2(qy0d, av.y, r0);
            r0 = fma2(qz0d, bv.x, r0);
            unsigned long long r1 = fma2(qx1d, av.x, bv.y);
            r1 = fma2(qy1d, av.y, r1);
            r1 = fma2(qz1d, bv.x, r1);

            float ta0, tb0, ta1, tb1;
            unpack2(r0, ta0, tb0);
            unpack2(r1, ta1, tb1);

            const int   s   = sbase + s0 + 2 * up;
            const float fia = __int_as_float(s);
            const float fib = __int_as_float(s + 1);

            score_op(a0, ta0, thr0, fia);
            score_op(a0, tb0, thr0, fib);
            score_op(a1, ta1, thr1, fia);
            score_op(a1, tb1, thr1, fib);
        }
        // Warp-uniform fold check (all lanes converged: stores are predicated)
        if (__any_sync(0xffffffffu, (a0 >= lim0) || (a1 >= lim1))) {
            const int cnt0 = (int)((a0 - base0) >> 11);
            const int cnt1 = (int)((a1 - base1) >> 11);
            for (int j = 0; j < cnt0; j++) {
                float2 e = buf0[j * THREADS + tid];
                pair_insert(e.x, __float_as_int(e.y), v0, i0);
            }
            for (int j = 0; j < cnt1; j++) {
                float2 e = buf1[j * THREADS + tid];
                pair_insert(e.x, __float_as_int(e.y), v1, i1);
            }
            a0 = base0; a1 = base1;
            thr0 = v0[KNN-1]; thr1 = v1[KNN-1];
        }
    }
    // final drain
    {
        const int cnt0 = (int)((a0 - base0) >> 11);
        const int cnt1 = (int)((a1 - base1) >> 11);
        for (int j = 0; j < cnt0; j++) {
            float2 e = buf0[j * THREADS + tid];
            pair_insert(e.x, __float_as_int(e.y), v0, i0);
        }
        for (int j = 0; j < cnt1; j++) {
            float2 e = buf1[j * THREADS + tid];
            pair_insert(e.x, __float_as_int(e.y), v1, i1);
        }
    }

    // Publish sorted partial top-8s, coalesced [split][j][q] layout
#pragma unroll
    for (int j = 0; j < KNN; j++) {
        g_part[(split * KNN + j) * NQ_TOTAL + q0] =
            make_float2(v0[j], __int_as_float(i0[j]));
        g_part[(split * KNN + j) * NQ_TOTAL + q1] =
            make_float2(v1[j], __int_as_float(i1[j]));
    }
}

// ---------------------------------------------------------------------------
// Finalize: merge the eight sorted slices, exact distances (no cancellation),
// IDW weights. One thread per query.
// ---------------------------------------------------------------------------
__global__ void __launch_bounds__(256) finalize_kernel(const float* __restrict__ qc,
                                                       const float* __restrict__ sc)
{
    const int q = blockIdx.x * 256 + threadIdx.x;

    float v[KNN]; int ii[KNN];
#pragma unroll
    for (int j = 0; j < KNN; j++) {            // split 0 list already sorted desc
        float2 e = g_part[j * NQ_TOTAL + q];
        v[j]  = e.x;
        ii[j] = __float_as_int(e.y);
    }
#pragma unroll
    for (int sp = 1; sp < NSPLIT; sp++) {
#pragma unroll
        for (int j = 0; j < KNN; j++) {
            float2 e = g_part[(sp * KNN + j) * NQ_TOTAL + q];
            pair_insert(e.x, __float_as_int(e.y), v, ii);
        }
    }

    const float qx = qc[3*q+0];
    const float qy = qc[3*q+1];
    const float qz = qc[3*q+2];

    float w[KNN];
    float wsum = 0.0f;
#pragma unroll
    for (int j = 0; j < KNN; j++) {
        const int s = ii[j];
        float dx = qx - sc[3*s+0];
        float dy = qy - sc[3*s+1];
        float dz = qz - sc[3*s+2];
        float d  = sqrtf(fmaf(dx, dx, fmaf(dy, dy, dz*dz)));
        float wj = 1.0f / (d + 1e-8f);
        w[j] = wj;
        wsum += wj;
    }
    const float inv = 1.0f / wsum;
#pragma unroll
    for (int j = 0; j < KNN; j++) {
        g_w  [q*KNN + j] = w[j] * inv;
        g_idx[q*KNN + j] = ii[j];
    }
}

// ---------------------------------------------------------------------------
// Gather kernel: weighted feature gather. One warp per query, coalesced float4.
// (At the L2 roofline: 268 MB of L2-resident reads ~ its measured 21 us.)
// ---------------------------------------------------------------------------
__global__ void __launch_bounds__(256) gather_kernel(const float* __restrict__ feats,
                                                     float* __restrict__ out)
{
    const int gw   = (blockIdx.x * 256 + threadIdx.x) >> 5;  // global query id
    const int lane = threadIdx.x & 31;
    const int b    = gw >> 13;                               // / 8192

    const float4* __restrict__ fb =
        reinterpret_cast<const float4*>(feats) + (size_t)b * NS * FDIM4;

    float4 a0 = make_float4(0.f, 0.f, 0.f, 0.f);
    float4 a1 = make_float4(0.f, 0.f, 0.f, 0.f);

#pragma unroll
    for (int k = 0; k < KNN; k++) {
        const float wk = g_w  [gw*KNN + k];   // same addr across warp -> broadcast
        const int   id = g_idx[gw*KNN + k];
        const float4* __restrict__ fr = fb + (size_t)id * FDIM4;
        float4 f0 = fr[lane];
        float4 f1 = fr[lane + 32];
        a0.x = fmaf(wk, f0.x, a0.x); a0.y = fmaf(wk, f0.y, a0.y);
        a0.z = fmaf(wk, f0.z, a0.z); a0.w = fmaf(wk, f0.w, a0.w);
        a1.x = fmaf(wk, f1.x, a1.x); a1.y = fmaf(wk, f1.y, a1.y);
        a1.z = fmaf(wk, f1.z, a1.z); a1.w = fmaf(wk, f1.w, a1.w);
    }

    float4* __restrict__ o = reinterpret_cast<float4*>(out) + (size_t)gw * FDIM4;
    o[lane]      = a0;
    o[lane + 32] = a1;
}

// ---------------------------------------------------------------------------
// Launch: three dependent kernels, graph-capturable, allocation-free.
// ---------------------------------------------------------------------------
extern "C" void kernel_launch(void* const* d_in, const int* in_sizes, int n_in,
                              void* d_out, int out_size)
{
    const float* qc = (const float*)d_in[0];   // query_coords   (B, NQ, 3)
    const float* sc = (const float*)d_in[1];   // sensor_coords  (NS, 3)
    const float* ft = (const float*)d_in[2];   // sensor_features(B, NS, F)

    // 8 KB tile + 2 * 28 KB candidate buffers = 64 KB -> 3 blocks/SM
    const int smem = QUARTER * 16 + 2 * DEPTH * THREADS * 8;

    cudaFuncSetAttribute(scan_kernel,
                         cudaFuncAttributeMaxDynamicSharedMemorySize, smem);

    scan_kernel    <<<(NQ_TOTAL / QPB) * NSPLIT, THREADS, smem>>>(qc, sc);
    finalize_kernel<<< NQ_TOTAL / 256, 256>>>(qc, sc);
    gather_kernel  <<<(NQ_TOTAL * 32) / 256, 256>>>(ft, (float*)d_out);
}

// round 11
// speedup vs baseline: 1.1693x; 1.1693x over previous
#include <cuda_runtime.h>
#include <cuda_bf16.h>

// Problem constants (fixed by the problem spec)
#define NS        4096
#define NQ_TOTAL  32768     // B * N_Q
#define KNN       8
#define FDIM      256
#define FDIM4     (FDIM/4)

#define NSPLIT    4         // sensor quarters per query
#define QUARTER   1024      // sensors per block (NS / NSPLIT)
#define THREADS   256
#define QPT       2         // queries per thread
#define QPB       (THREADS*QPT)   // 512 queries per block-group
#define GROUP     16        // sensors per vote group (two 8-sensor phases)
#define PHASE     8         // sensors per compute phase (register pressure)
#define DEPTH     20        // smem candidate slots per (thread,query)
#define TRIG      4         // fold trigger; entering a group cnt<=3 -> max slot 19
#define SLOTB     (THREADS*8)     // 2048 bytes between buffer slots

// Inter-kernel scratch (device globals: allowed; no allocation)
__device__ float2 g_part[NSPLIT * KNN * NQ_TOTAL];  // [split][j][q], 8 MB
__device__ float  g_w  [NQ_TOTAL * KNN];
__device__ int    g_idx[NQ_TOTAL * KNN];

// Branchless sorted insert of (x, xi) into descending (value, idx) top-8 list.
__device__ __forceinline__ void pair_insert(float x, int xi,
                                            float (&v)[KNN], int (&ii)[KNN])
{
#pragma unroll
    for (int j = KNN - 1; j >= 1; --j) {   // v[j-1] still old value here
        bool pjm = x > v[j-1];
        bool pj  = x > v[j];
        v[j]  = pjm ? v[j-1]  : (pj ? x  : v[j]);
        ii[j] = pjm ? ii[j-1] : (pj ? xi : ii[j]);
    }
    bool p0 = x > v[0];
    v[0]  = p0 ? x  : v[0];
    ii[0] = p0 ? xi : ii[0];
}

// Fused hit op: ONE compare feeds both the predicated store and the
// predicated cursor bump. 3 instructions, zero branches, no dup FSETP/SEL/IADD.
__device__ __forceinline__ void score_op(unsigned& a, float t, float thr, float fi)
{
    asm volatile(
        "{\n\t"
        ".reg .pred p;\n\t"
        "setp.gt.f32 p, %1, %2;\n\t"
        "@p st.shared.v2.f32 [%0], {%1, %3};\n\t"
        "@p add.u32 %0, %0, %4;\n\t"
        "}"
        : "+r"(a)
        : "f"(t), "f"(thr), "f"(fi), "r"((unsigned)SLOTB)
        : "memory");
}

// ---------------------------------------------------------------------------
// Scan kernel. Block = (query group of 512) x (sensor quarter of 1024).
// Each thread owns 2 queries; one broadcast LDS.128 feeds both dot products
// (scalar FFMA only -- packed f32x2 loses to its own register marshaling).
// Score t = q.s - 0.5|s|^2 (max == nearest). Hit handling is the fused
// 3-instruction predicated op. Warp-uniform folds every 16 sensors drain the
// smem buffer into the register-resident sorted top-8 and tighten thr.
// ---------------------------------------------------------------------------
__global__ void __launch_bounds__(THREADS) scan_kernel(const float* __restrict__ qc,
                                                       const float* __restrict__ sc)
{
    extern __shared__ float4 tile[];                          // QUARTER*16B = 16 KB
    float2* buf0 = reinterpret_cast<float2*>(tile + QUARTER); // [DEPTH][THREADS] 40 KB
    float2* buf1 = buf0 + DEPTH * THREADS;                    // [DEPTH][THREADS] 40 KB

    const int tid    = threadIdx.x;
    const int split  = blockIdx.x & (NSPLIT - 1);
    const int qgroup = blockIdx.x >> 2;
    const int sbase  = split * QUARTER;
    const int q0     = qgroup * QPB + tid;
    const int q1     = q0 + THREADS;

    // Stage + preprocess this quarter's sensors: (x, y, z, 0.5*|s|^2)
    for (int i = tid; i < QUARTER; i += THREADS) {
        const int s = sbase + i;
        float sx = sc[3*s+0], sy = sc[3*s+1], sz = sc[3*s+2];
        tile[i] = make_float4(sx, sy, sz, 0.5f * (sx*sx + sy*sy + sz*sz));
    }
    __syncthreads();

    const float qx0 = qc[3*q0+0], qy0 = qc[3*q0+1], qz0 = qc[3*q0+2];
    const float qx1 = qc[3*q1+0], qy1 = qc[3*q1+1], qz1 = qc[3*q1+2];

    float v0[KNN], v1[KNN];
    int   i0[KNN], i1[KNN];
#pragma unroll
    for (int j = 0; j < KNN; j++) {
        v0[j] = -3.0e38f; i0[j] = 0;
        v1[j] = -3.0e38f; i1[j] = 0;
    }

    const unsigned base0 = (unsigned)__cvta_generic_to_shared(buf0) + tid * 8u;
    const unsigned base1 = (unsigned)__cvta_generic_to_shared(buf1) + tid * 8u;
    const unsigned lim0  = base0 + TRIG * SLOTB;
    const unsigned lim1  = base1 + TRIG * SLOTB;

    unsigned a0 = base0, a1 = base1;
    float thr0 = -3.0e38f, thr1 = -3.0e38f;

    for (int s0 = 0; s0 < QUARTER; s0 += GROUP) {
        // Two compute/store phases of 8 sensors (keeps live regs near R8 level)
#pragma unroll
        for (int ph = 0; ph < GROUP / PHASE; ph++) {
            const int pb = s0 + ph * PHASE;
            float t0[PHASE], t1[PHASE];
#pragma unroll
            for (int u = 0; u < PHASE; u++) {
                float4 h = tile[pb + u];
                t0[u] = fmaf(qx0, h.x, fmaf(qy0, h.y, fmaf(qz0, h.z, -h.w)));
                t1[u] = fmaf(qx1, h.x, fmaf(qy1, h.y, fmaf(qz1, h.z, -h.w)));
            }
#pragma unroll
            for (int u = 0; u < PHASE; u++) {
                const float fi = __int_as_float(sbase + pb + u);
                score_op(a0, t0[u], thr0, fi);
                score_op(a1, t1[u], thr1, fi);
            }
        }
        // Warp-uniform fold check once per 16 sensors (lanes stay converged:
        // all stores above are predicated single instructions)
        if (__any_sync(0xffffffffu, (a0 >= lim0) || (a1 >= lim1))) {
            const int cnt0 = (int)((a0 - base0) >> 11);
            const int cnt1 = (int)((a1 - base1) >> 11);
            for (int j = 0; j < cnt0; j++) {
                float2 e = buf0[j * THREADS + tid];
                pair_insert(e.x, __float_as_int(e.y), v0, i0);
            }
            for (int j = 0; j < cnt1; j++) {
                float2 e = buf1[j * THREADS + tid];
                pair_insert(e.x, __float_as_int(e.y), v1, i1);
            }
            a0 = base0; a1 = base1;
            thr0 = v0[KNN-1]; thr1 = v1[KNN-1];
        }
    }
    // final drain
    {
        const int cnt0 = (int)((a0 - base0) >> 11);
        const int cnt1 = (int)((a1 - base1) >> 11);
        for (int j = 0; j < cnt0; j++) {
            float2 e = buf0[j * THREADS + tid];
            pair_insert(e.x, __float_as_int(e.y), v0, i0);
        }
        for (int j = 0; j < cnt1; j++) {
            float2 e = buf1[j * THREADS + tid];
            pair_insert(e.x, __float_as_int(e.y), v1, i1);
        }
    }

    // Publish sorted partial top-8s, coalesced [split][j][q] layout
#pragma unroll
    for (int j = 0; j < KNN; j++) {
        g_part[(split * KNN + j) * NQ_TOTAL + q0] =
            make_float2(v0[j], __int_as_float(i0[j]));
        g_part[(split * KNN + j) * NQ_TOTAL + q1] =
            make_float2(v1[j], __int_as_float(i1[j]));
    }
}

// ---------------------------------------------------------------------------
// Finalize: merge the four sorted quarters, exact distances (no cancellation),
// IDW weights. One thread per query.
// ---------------------------------------------------------------------------
__global__ void __launch_bounds__(256) finalize_kernel(const float* __restrict__ qc,
                                                       const float* __restrict__ sc)
{
    const int q = blockIdx.x * 256 + threadIdx.x;

    float v[KNN]; int ii[KNN];
#pragma unroll
    for (int j = 0; j < KNN; j++) {            // split 0 list already sorted desc
        float2 e = g_part[j * NQ_TOTAL + q];
        v[j]  = e.x;
        ii[j] = __float_as_int(e.y);
    }
#pragma unroll
    for (int sp = 1; sp < NSPLIT; sp++) {
#pragma unroll
        for (int j = 0; j < KNN; j++) {
            float2 e = g_part[(sp * KNN + j) * NQ_TOTAL + q];
            pair_insert(e.x, __float_as_int(e.y), v, ii);
        }
    }

    const float qx = qc[3*q+0];
    const float qy = qc[3*q+1];
    const float qz = qc[3*q+2];

    float w[KNN];
    float wsum = 0.0f;
#pragma unroll
    for (int j = 0; j < KNN; j++) {
        const int s = ii[j];
        float dx = qx - sc[3*s+0];
        float dy = qy - sc[3*s+1];
        float dz = qz - sc[3*s+2];
        float d  = sqrtf(fmaf(dx, dx, fmaf(dy, dy, dz*dz)));
        float wj = 1.0f / (d + 1e-8f);
        w[j] = wj;
        wsum += wj;
    }
    const float inv = 1.0f / wsum;
#pragma unroll
    for (int j = 0; j < KNN; j++) {
        g_w  [q*KNN + j] = w[j] * inv;
        g_idx[q*KNN + j] = ii[j];
    }
}

// ---------------------------------------------------------------------------
// Gather kernel: weighted feature gather. One warp per query, coalesced float4.
// (At the L2 roofline: 268 MB of L2-resident reads ~ its measured 21 us.)
// ---------------------------------------------------------------------------
__global__ void __launch_bounds__(256) gather_kernel(const float* __restrict__ feats,
                                                     float* __restrict__ out)
{
    const int gw   = (blockIdx.x * 256 + threadIdx.x) >> 5;  // global query id
    const int lane = threadIdx.x & 31;
    const int b    = gw >> 13;                               // / 8192

    const float4* __restrict__ fb =
        reinterpret_cast<const float4*>(feats) + (size_t)b * NS * FDIM4;

    float4 a0 = make_float4(0.f, 0.f, 0.f, 0.f);
    float4 a1 = make_float4(0.f, 0.f, 0.f, 0.f);

#pragma unroll
    for (int k = 0; k < KNN; k++) {
        const float wk = g_w  [gw*KNN + k];   // same addr across warp -> broadcast
        const int   id = g_idx[gw*KNN + k];
        const float4* __restrict__ fr = fb + (size_t)id * FDIM4;
        float4 f0 = fr[lane];
        float4 f1 = fr[lane + 32];
        a0.x = fmaf(wk, f0.x, a0.x); a0.y = fmaf(wk, f0.y, a0.y);
        a0.z = fmaf(wk, f0.z, a0.z); a0.w = fmaf(wk, f0.w, a0.w);
        a1.x = fmaf(wk, f1.x, a1.x); a1.y = fmaf(wk, f1.y, a1.y);
        a1.z = fmaf(wk, f1.z, a1.z); a1.w = fmaf(wk, f1.w, a1.w);
    }

    float4* __restrict__ o = reinterpret_cast<float4*>(out) + (size_t)gw * FDIM4;
    o[lane]      = a0;
    o[lane + 32] = a1;
}

// ---------------------------------------------------------------------------
// Launch: three dependent kernels, graph-capturable, allocation-free.
// ---------------------------------------------------------------------------
extern "C" void kernel_launch(void* const* d_in, const int* in_sizes, int n_in,
                              void* d_out, int out_size)
{
    const float* qc = (const float*)d_in[0];   // query_coords   (B, NQ, 3)
    const float* sc = (const float*)d_in[1];   // sensor_coords  (NS, 3)
    const float* ft = (const float*)d_in[2];   // sensor_features(B, NS, F)

    // 16 KB tile + 2 * 40 KB candidate buffers = 96 KB -> 2 blocks/SM
    const int smem = QUARTER * 16 + 2 * DEPTH * THREADS * 8;

    cudaFuncSetAttribute(scan_kernel,
                         cudaFuncAttributeMaxDynamicSharedMemorySize, smem);

    scan_kernel    <<<(NQ_TOTAL / QPB) * NSPLIT, THREADS, smem>>>(qc, sc);
    finalize_kernel<<< NQ_TOTAL / 256, 256>>>(qc, sc);
    gather_kernel  <<<(NQ_TOTAL * 32) / 256, 256>>>(ft, (float*)d_out);
}

// round 12
// speedup vs baseline: 1.1732x; 1.0033x over previous
#include <cuda_runtime.h>
#include <cuda_bf16.h>

// Problem constants (fixed by the problem spec)
#define NS        4096
#define NQ_TOTAL  32768     // B * N_Q
#define KNN       8
#define FDIM      256
#define FDIM4     (FDIM/4)

#define NSPLIT    4         // sensor quarters per query
#define QUARTER   1024      // sensors per block (NS / NSPLIT)
#define THREADS   256
#define QPT       2         // queries per thread
#define QPB       (THREADS*QPT)   // 512 queries per block-group
#define GROUP     16        // sensors per vote group (two 8-sensor phases)
#define PHASE     8         // sensors per compute phase (register pressure)
#define DEPTH     20        // smem candidate slots per (thread,query)
#define TRIG      4         // fold trigger; entering a group cnt<=3 -> max slot 19
#define SLOTB     (THREADS*8)     // 2048 bytes between buffer slots

// Inter-kernel scratch (device globals: allowed; no allocation)
__device__ float2 g_part[NSPLIT * KNN * NQ_TOTAL];  // [split][j][q], 8 MB
__device__ float  g_w  [NQ_TOTAL * KNN];
__device__ int    g_idx[NQ_TOTAL * KNN];

// Branchless sorted insert of (x, xi) into descending (value, idx) top-8 list.
__device__ __forceinline__ void pair_insert(float x, int xi,
                                            float (&v)[KNN], int (&ii)[KNN])
{
#pragma unroll
    for (int j = KNN - 1; j >= 1; --j) {   // v[j-1] still old value here
        bool pjm = x > v[j-1];
        bool pj  = x > v[j];
        v[j]  = pjm ? v[j-1]  : (pj ? x  : v[j]);
        ii[j] = pjm ? ii[j-1] : (pj ? xi : ii[j]);
    }
    bool p0 = x > v[0];
    v[0]  = p0 ? x  : v[0];
    ii[0] = p0 ? xi : ii[0];
}

// Fused hit op: ONE compare feeds both the predicated store and the
// predicated cursor bump. 3 instructions, zero branches, no dup FSETP/SEL/IADD.
__device__ __forceinline__ void score_op(unsigned& a, float t, float thr, float fi)
{
    asm volatile(
        "{\n\t"
        ".reg .pred p;\n\t"
        "setp.gt.f32 p, %1, %2;\n\t"
        "@p st.shared.v2.f32 [%0], {%1, %3};\n\t"
        "@p add.u32 %0, %0, %4;\n\t"
        "}"
        : "+r"(a)
        : "f"(t), "f"(thr), "f"(fi), "r"((unsigned)SLOTB)
        : "memory");
}

// ---------------------------------------------------------------------------
// Scan kernel. Block = (query group of 512) x (sensor quarter of 1024).
// Each thread owns 2 queries; one broadcast LDS.128 feeds both dot products
// (scalar FFMA only -- packed f32x2 loses to its own register marshaling).
// Score t = q.s - 0.5|s|^2 (max == nearest). Hit handling is the fused
// 3-instruction predicated op. Warp-uniform folds every 16 sensors drain the
// smem buffer into the register-resident sorted top-8 and tighten thr.
// ---------------------------------------------------------------------------
__global__ void __launch_bounds__(THREADS) scan_kernel(const float* __restrict__ qc,
                                                       const float* __restrict__ sc)
{
    extern __shared__ float4 tile[];                          // QUARTER*16B = 16 KB
    float2* buf0 = reinterpret_cast<float2*>(tile + QUARTER); // [DEPTH][THREADS] 40 KB
    float2* buf1 = buf0 + DEPTH * THREADS;                    // [DEPTH][THREADS] 40 KB

    const int tid    = threadIdx.x;
    const int split  = blockIdx.x & (NSPLIT - 1);
    const int qgroup = blockIdx.x >> 2;
    const int sbase  = split * QUARTER;
    const int q0     = qgroup * QPB + tid;
    const int q1     = q0 + THREADS;

    // Stage + preprocess this quarter's sensors: (x, y, z, 0.5*|s|^2)
    for (int i = tid; i < QUARTER; i += THREADS) {
        const int s = sbase + i;
        float sx = sc[3*s+0], sy = sc[3*s+1], sz = sc[3*s+2];
        tile[i] = make_float4(sx, sy, sz, 0.5f * (sx*sx + sy*sy + sz*sz));
    }
    __syncthreads();

    const float qx0 = qc[3*q0+0], qy0 = qc[3*q0+1], qz0 = qc[3*q0+2];
    const float qx1 = qc[3*q1+0], qy1 = qc[3*q1+1], qz1 = qc[3*q1+2];

    float v0[KNN], v1[KNN];
    int   i0[KNN], i1[KNN];
#pragma unroll
    for (int j = 0; j < KNN; j++) {
        v0[j] = -3.0e38f; i0[j] = 0;
        v1[j] = -3.0e38f; i1[j] = 0;
    }

    const unsigned base0 = (unsigned)__cvta_generic_to_shared(buf0) + tid * 8u;
    const unsigned base1 = (unsigned)__cvta_generic_to_shared(buf1) + tid * 8u;
    const unsigned lim0  = base0 + TRIG * SLOTB;
    const unsigned lim1  = base1 + TRIG * SLOTB;

    unsigned a0 = base0, a1 = base1;
    float thr0 = -3.0e38f, thr1 = -3.0e38f;

    for (int s0 = 0; s0 < QUARTER; s0 += GROUP) {
        // Two compute/store phases of 8 sensors (keeps live regs near R8 level)
#pragma unroll
        for (int ph = 0; ph < GROUP / PHASE; ph++) {
            const int pb = s0 + ph * PHASE;
            float t0[PHASE], t1[PHASE];
#pragma unroll
            for (int u = 0; u < PHASE; u++) {
                float4 h = tile[pb + u];
                t0[u] = fmaf(qx0, h.x, fmaf(qy0, h.y, fmaf(qz0, h.z, -h.w)));
                t1[u] = fmaf(qx1, h.x, fmaf(qy1, h.y, fmaf(qz1, h.z, -h.w)));
            }
#pragma unroll
            for (int u = 0; u < PHASE; u++) {
                const float fi = __int_as_float(sbase + pb + u);
                score_op(a0, t0[u], thr0, fi);
                score_op(a1, t1[u], thr1, fi);
            }
        }
        // Warp-uniform fold check once per 16 sensors (lanes stay converged:
        // all stores above are predicated single instructions)
        if (__any_sync(0xffffffffu, (a0 >= lim0) || (a1 >= lim1))) {
            const int cnt0 = (int)((a0 - base0) >> 11);
            const int cnt1 = (int)((a1 - base1) >> 11);
            for (int j = 0; j < cnt0; j++) {
                float2 e = buf0[j * THREADS + tid];
                pair_insert(e.x, __float_as_int(e.y), v0, i0);
            }
            for (int j = 0; j < cnt1; j++) {
                float2 e = buf1[j * THREADS + tid];
                pair_insert(e.x, __float_as_int(e.y), v1, i1);
            }
            a0 = base0; a1 = base1;
            thr0 = v0[KNN-1]; thr1 = v1[KNN-1];
        }
    }
    // final drain
    {
        const int cnt0 = (int)((a0 - base0) >> 11);
        const int cnt1 = (int)((a1 - base1) >> 11);
        for (int j = 0; j < cnt0; j++) {
            float2 e = buf0[j * THREADS + tid];
            pair_insert(e.x, __float_as_int(e.y), v0, i0);
        }
        for (int j = 0; j < cnt1; j++) {
            float2 e = buf1[j * THREADS + tid];
            pair_insert(e.x, __float_as_int(e.y), v1, i1);
        }
    }

    // Publish sorted partial top-8s, coalesced [split][j][q] layout
#pragma unroll
    for (int j = 0; j < KNN; j++) {
        g_part[(split * KNN + j) * NQ_TOTAL + q0] =
            make_float2(v0[j], __int_as_float(i0[j]));
        g_part[(split * KNN + j) * NQ_TOTAL + q1] =
            make_float2(v1[j], __int_as_float(i1[j]));
    }
}

// ---------------------------------------------------------------------------
// Finalize: merge the four sorted quarters, exact distances (no cancellation),
// IDW weights. One thread per query.
// ---------------------------------------------------------------------------
__global__ void __launch_bounds__(256) finalize_kernel(const float* __restrict__ qc,
                                                       const float* __restrict__ sc)
{
    const int q = blockIdx.x * 256 + threadIdx.x;

    float v[KNN]; int ii[KNN];
#pragma unroll
    for (int j = 0; j < KNN; j++) {            // split 0 list already sorted desc
        float2 e = g_part[j * NQ_TOTAL + q];
        v[j]  = e.x;
        ii[j] = __float_as_int(e.y);
    }
#pragma unroll
    for (int sp = 1; sp < NSPLIT; sp++) {
#pragma unroll
        for (int j = 0; j < KNN; j++) {
            float2 e = g_part[(sp * KNN + j) * NQ_TOTAL + q];
            pair_insert(e.x, __float_as_int(e.y), v, ii);
        }
    }

    const float qx = qc[3*q+0];
    const float qy = qc[3*q+1];
    const float qz = qc[3*q+2];

    float w[KNN];
    float wsum = 0.0f;
#pragma unroll
    for (int j = 0; j < KNN; j++) {
        const int s = ii[j];
        float dx = qx - sc[3*s+0];
        float dy = qy - sc[3*s+1];
        float dz = qz - sc[3*s+2];
        float d  = sqrtf(fmaf(dx, dx, fmaf(dy, dy, dz*dz)));
        float wj = 1.0f / (d + 1e-8f);
        w[j] = wj;
        wsum += wj;
    }
    const float inv = 1.0f / wsum;
#pragma unroll
    for (int j = 0; j < KNN; j++) {
        g_w  [q*KNN + j] = w[j] * inv;
        g_idx[q*KNN + j] = ii[j];
    }
}

// ---------------------------------------------------------------------------
// Gather kernel: weighted feature gather. One warp per query, coalesced float4.
// (At the L2 roofline: 268 MB of L2-resident reads ~ its measured 21 us.)
// ---------------------------------------------------------------------------
__global__ void __launch_bounds__(256) gather_kernel(const float* __restrict__ feats,
                                                     float* __restrict__ out)
{
    const int gw   = (blockIdx.x * 256 + threadIdx.x) >> 5;  // global query id
    const int lane = threadIdx.x & 31;
    const int b    = gw >> 13;                               // / 8192

    const float4* __restrict__ fb =
        reinterpret_cast<const float4*>(feats) + (size_t)b * NS * FDIM4;

    float4 a0 = make_float4(0.f, 0.f, 0.f, 0.f);
    float4 a1 = make_float4(0.f, 0.f, 0.f, 0.f);

#pragma unroll
    for (int k = 0; k < KNN; k++) {
        const float wk = g_w  [gw*KNN + k];   // same addr across warp -> broadcast
        const int   id = g_idx[gw*KNN + k];
        const float4* __restrict__ fr = fb + (size_t)id * FDIM4;
        float4 f0 = fr[lane];
        float4 f1 = fr[lane + 32];
        a0.x = fmaf(wk, f0.x, a0.x); a0.y = fmaf(wk, f0.y, a0.y);
        a0.z = fmaf(wk, f0.z, a0.z); a0.w = fmaf(wk, f0.w, a0.w);
        a1.x = fmaf(wk, f1.x, a1.x); a1.y = fmaf(wk, f1.y, a1.y);
        a1.z = fmaf(wk, f1.z, a1.z); a1.w = fmaf(wk, f1.w, a1.w);
    }

    float4* __restrict__ o = reinterpret_cast<float4*>(out) + (size_t)gw * FDIM4;
    o[lane]      = a0;
    o[lane + 32] = a1;
}

// ---------------------------------------------------------------------------
// Launch: three dependent kernels, graph-capturable, allocation-free.
// ---------------------------------------------------------------------------
extern "C" void kernel_launch(void* const* d_in, const int* in_sizes, int n_in,
                              void* d_out, int out_size)
{
    const float* qc = (const float*)d_in[0];   // query_coords   (B, NQ, 3)
    const float* sc = (const float*)d_in[1];   // sensor_coords  (NS, 3)
    const float* ft = (const float*)d_in[2];   // sensor_features(B, NS, F)

    // 16 KB tile + 2 * 40 KB candidate buffers = 96 KB -> 2 blocks/SM
    const int smem = QUARTER * 16 + 2 * DEPTH * THREADS * 8;

    cudaFuncSetAttribute(scan_kernel,
                         cudaFuncAttributeMaxDynamicSharedMemorySize, smem);

    scan_kernel    <<<(NQ_TOTAL / QPB) * NSPLIT, THREADS, smem>>>(qc, sc);
    finalize_kernel<<< NQ_TOTAL / 256, 256>>>(qc, sc);
    gather_kernel  <<<(NQ_TOTAL * 32) / 256, 256>>>(ft, (float*)d_out);
}